// round 16
// baseline (speedup 1.0000x reference)
#include <cuda_runtime.h>
#include <cuda_bf16.h>
#include <math.h>
#include <stdint.h>

#define NN 4096          // D*W*H = 16*16*16
#define LL 21            // labels
#define LN (LL * NN)

// ---------------- device scratch ----------------
__device__ __nv_bfloat16 g_Kb[16777216];   // 4096x4096 bilateral kernel bf16 (32 MB)
__device__ float         g_F[NN * 8];      // features f0..f5, h, pad
__device__ float         g_q[LN];          // softmax out (fp32, spatial path)
__device__ __nv_bfloat16 g_qb[24 * NN];    // bf16 q rows 0..20, row21=ones, 22..23=0
__device__ float         g_A[LN];          // spatial filter result
__device__ float         g_P[32 * NN];     // bilateral GEMM out, column-major P[c][n]; c=21 = normalizer
__device__ float         g_Msp[LL * LL];
__device__ float         g_Mbi[LL * LL];
__device__ float         g_G[16];
__device__ float         g_S[16];

// ---------------- HMMA helper (plain sm_103 PTX legal) ----------------
__device__ __forceinline__ void mma16816(float* c, uint32_t a0, uint32_t a1,
                                         uint32_t a2, uint32_t a3,
                                         uint32_t b0, uint32_t b1) {
    asm volatile(
        "mma.sync.aligned.m16n8k16.row.col.f32.bf16.bf16.f32 "
        "{%0,%1,%2,%3}, {%4,%5,%6,%7}, {%8,%9}, {%0,%1,%2,%3};"
        : "+f"(c[0]), "+f"(c[1]), "+f"(c[2]), "+f"(c[3])
        : "r"(a0), "r"(a1), "r"(a2), "r"(a3), "r"(b0), "r"(b1));
}

// exp(x) for x in [-0.25, 0]: 4th-order Taylor, max rel err ~7e-6 (<< bf16 quantization)
__device__ __forceinline__ float exp_small(float x) {
    float p = 0.041666667f;              // 1/24
    p = fmaf(p, x, 0.16666667f);         // 1/6
    p = fmaf(p, x, 0.5f);
    p = fmaf(p, x, 1.0f);
    p = fmaf(p, x, 1.0f);
    return p;
}

// ---------------- features + initial softmax + qb + zero P + setup (one launch) ----------------
__global__ void __launch_bounds__(128) featsm_k(const float* __restrict__ img,
                                                const float* __restrict__ logits,
                                                const float* __restrict__ wsp,
                                                const float* __restrict__ wbi,
                                                const float* __restrict__ comp) {
    if (blockIdx.x == 32) {
        int t0 = threadIdx.x;
        if (t0 < 16) {
            g_G[t0] = expf(-0.5f * (float)(t0 * t0));
            float s = 0.f;
            for (int u = 0; u < 16; u++) {
                int d = t0 - u;
                s += expf(-0.5f * (float)(d * d));
            }
            g_S[t0] = s;
        }
        for (int t = t0; t < LL * LL; t += 128) {
            int l = t / LL, m = t % LL;
            float s1 = 0.f, s2 = 0.f;
            for (int k = 0; k < LL; k++) {
                float c = comp[l * LL + k];
                s1 += c * wsp[k * LL + m];
                s2 += c * wbi[k * LL + m];
            }
            g_Msp[t] = s1;
            g_Mbi[t] = s2;
        }
        return;
    }
    int n = blockIdx.x * 128 + threadIdx.x;
    {
        float z = (float)(n >> 8);
        float y = (float)((n >> 4) & 15);
        float x = (float)(n & 15);
        const float ia = 1.f / 67.f, ib = 1.f / 3.f;
        float f0 = z * ia, f1 = y * ia, f2 = x * ia;
        float f3 = img[n] * ib;
        float f4 = img[NN + n] * ib;
        float f5 = img[2 * NN + n] * ib;
        float h = -0.5f * (f0 * f0 + f1 * f1 + f2 * f2 + f3 * f3 + f4 * f4 + f5 * f5);
        float* p = g_F + (size_t)n * 8;
        p[0] = f0; p[1] = f1; p[2] = f2; p[3] = f3; p[4] = f4; p[5] = f5; p[6] = h; p[7] = 0.f;
        g_qb[21 * NN + n] = __float2bfloat16(1.0f);
        g_qb[22 * NN + n] = __float2bfloat16(0.0f);
        g_qb[23 * NN + n] = __float2bfloat16(0.0f);
    }
    float v[LL];
    float m = -1e30f;
#pragma unroll
    for (int l = 0; l < LL; l++) {
        v[l] = logits[l * NN + n];
        m = fmaxf(m, v[l]);
    }
    float s = 0.f;
#pragma unroll
    for (int l = 0; l < LL; l++) {
        v[l] = __expf(v[l] - m);
        s += v[l];
    }
    float inv = 1.f / s;
#pragma unroll
    for (int l = 0; l < LL; l++) {
        float q = v[l] * inv;
        g_q[l * NN + n] = q;
        g_qb[l * NN + n] = __float2bfloat16(q);
    }
#pragma unroll
    for (int m2 = 0; m2 < 32; m2++) g_P[m2 * NN + n] = 0.f;
}

// ---------------- K build: grid (16 jt, 128 ib), 128 thr; poly exp (no MUFU) ----------------
__global__ void __launch_bounds__(128) buildK_k() {
    int w = threadIdx.x >> 5;
    int lane = threadIdx.x & 31;
    int jb = blockIdx.x * 256 + lane * 8;
    int ibase = blockIdx.y * 32 + w * 8;

    float fj[8][7];
#pragma unroll
    for (int s = 0; s < 8; s++) {
        const float4* fp = (const float4*)(g_F + (size_t)(jb + s) * 8);
        float4 a = fp[0];
        float4 b = fp[1];
        fj[s][0] = a.x; fj[s][1] = a.y; fj[s][2] = a.z; fj[s][3] = a.w;
        fj[s][4] = b.x; fj[s][5] = b.y; fj[s][6] = b.z;
    }

#pragma unroll 2
    for (int ii = 0; ii < 8; ii++) {
        int i = ibase + ii;
        const float4* fp = (const float4*)(g_F + (size_t)i * 8);
        float4 a = fp[0];
        float4 b = fp[1];  // b.z = h_i
        float o[8];
#pragma unroll
        for (int s = 0; s < 8; s++) {
            float e = b.z + fj[s][6]
                    + a.x * fj[s][0] + a.y * fj[s][1] + a.z * fj[s][2]
                    + b.x * fj[s][4] + b.y * fj[s][5] + a.w * fj[s][3];
            o[s] = exp_small(e);   // e in [-0.242, 0] analytically
        }
        __nv_bfloat162 p0 = __floats2bfloat162_rn(o[0], o[1]);
        __nv_bfloat162 p1 = __floats2bfloat162_rn(o[2], o[3]);
        __nv_bfloat162 p2 = __floats2bfloat162_rn(o[4], o[5]);
        __nv_bfloat162 p3 = __floats2bfloat162_rn(o[6], o[7]);
        uint4 v;
        v.x = *(uint32_t*)&p0;
        v.y = *(uint32_t*)&p1;
        v.z = *(uint32_t*)&p2;
        v.w = *(uint32_t*)&p3;
        *(uint4*)(g_Kb + (size_t)i * NN + jb) = v;
    }
}

// ---------------- fused spatial + bilateral gemm. grid 533 x 256 thr ----------------
__global__ void __launch_bounds__(256) sg_k() {
    __shared__ float s0[4096];
    __shared__ float s1[4096];
    __shared__ float Gs[16];
    const int tid = threadIdx.x;
    const int bid = blockIdx.x;

    if (bid >= 512) {
        int l = bid - 512;
        if (tid < 16) Gs[tid] = g_G[tid];
        const float* src = g_q + (size_t)l * NN;
#pragma unroll
        for (int k = 0; k < 16; k++) s0[tid + k * 256] = src[tid + k * 256];
        __syncthreads();
#pragma unroll
        for (int k = 0; k < 16; k++) {
            int n = tid + k * 256;
            int x = n & 15, b = n - x;
            float a = 0.f;
#pragma unroll
            for (int tt = 0; tt < 16; tt++) {
                int d = x - tt; d = d < 0 ? -d : d;
                a += Gs[d] * s0[b + tt];
            }
            s1[n] = a;
        }
        __syncthreads();
#pragma unroll
        for (int k = 0; k < 16; k++) {
            int n = tid + k * 256;
            int y = (n >> 4) & 15, b = n - (y << 4);
            float a = 0.f;
#pragma unroll
            for (int tt = 0; tt < 16; tt++) {
                int d = y - tt; d = d < 0 ? -d : d;
                a += Gs[d] * s1[b + (tt << 4)];
            }
            s0[n] = a;
        }
        __syncthreads();
        float* dst = g_A + (size_t)l * NN;
#pragma unroll
        for (int k = 0; k < 16; k++) {
            int n = tid + k * 256;
            int z = n >> 8, b = n & 255;
            float a = 0.f;
#pragma unroll
            for (int tt = 0; tt < 16; tt++) {
                int d = z - tt; d = d < 0 ? -d : d;
                a += Gs[d] * s0[b + (tt << 8)];
            }
            dst[n] = a;
        }
        return;
    }

    // ---- gemm path: unit = (row-tile jt of 32 rows, ksplit of 128) ----
    int wid = tid >> 5, lane = tid & 31;
    int u = bid * 8 + wid;            // 0..4095
    int jt = u >> 5, ks = u & 31;
    int rb = jt * 32;
    int k0 = ks * 128;
    int g = lane >> 2, t = lane & 3;

    const __nv_bfloat16* pa0 = g_Kb + (size_t)(rb + g) * NN;
    const __nv_bfloat16* pa1 = g_Kb + (size_t)(rb + g + 8) * NN;
    const __nv_bfloat16* pa2 = g_Kb + (size_t)(rb + 16 + g) * NN;
    const __nv_bfloat16* pa3 = g_Kb + (size_t)(rb + 16 + g + 8) * NN;
    const __nv_bfloat16* pb0 = g_qb + (size_t)(g)*NN;
    const __nv_bfloat16* pb1 = g_qb + (size_t)(8 + g) * NN;
    const __nv_bfloat16* pb2 = g_qb + (size_t)(16 + g) * NN;

    float acc[2][3][4];
#pragma unroll
    for (int m = 0; m < 2; m++)
#pragma unroll
        for (int n = 0; n < 3; n++)
#pragma unroll
            for (int r = 0; r < 4; r++) acc[m][n][r] = 0.f;

#pragma unroll
    for (int kp = 0; kp < 4; kp++) {   // 4 pair-steps x 32 cols = 128
        int kc = k0 + kp * 32 + t * 8;
        uint4 A0 = *(const uint4*)(pa0 + kc);
        uint4 A1 = *(const uint4*)(pa1 + kc);
        uint4 A2 = *(const uint4*)(pa2 + kc);
        uint4 A3 = *(const uint4*)(pa3 + kc);
        uint4 B0 = *(const uint4*)(pb0 + kc);
        uint4 B1 = *(const uint4*)(pb1 + kc);
        uint4 B2 = *(const uint4*)(pb2 + kc);
        mma16816(acc[0][0], A0.x, A1.x, A0.y, A1.y, B0.x, B0.y);
        mma16816(acc[0][1], A0.x, A1.x, A0.y, A1.y, B1.x, B1.y);
        mma16816(acc[0][2], A0.x, A1.x, A0.y, A1.y, B2.x, B2.y);
        mma16816(acc[1][0], A2.x, A3.x, A2.y, A3.y, B0.x, B0.y);
        mma16816(acc[1][1], A2.x, A3.x, A2.y, A3.y, B1.x, B1.y);
        mma16816(acc[1][2], A2.x, A3.x, A2.y, A3.y, B2.x, B2.y);
        mma16816(acc[0][0], A0.z, A1.z, A0.w, A1.w, B0.z, B0.w);
        mma16816(acc[0][1], A0.z, A1.z, A0.w, A1.w, B1.z, B1.w);
        mma16816(acc[0][2], A0.z, A1.z, A0.w, A1.w, B2.z, B2.w);
        mma16816(acc[1][0], A2.z, A3.z, A2.w, A3.w, B0.z, B0.w);
        mma16816(acc[1][1], A2.z, A3.z, A2.w, A3.w, B1.z, B1.w);
        mma16816(acc[1][2], A2.z, A3.z, A2.w, A3.w, B2.z, B2.w);
    }

#pragma unroll
    for (int m = 0; m < 2; m++) {
        int r0 = rb + m * 16 + g;
#pragma unroll
        for (int n = 0; n < 3; n++) {
            int c = n * 8 + t * 2;
            if (c < 21) {
                atomicAdd(g_P + (size_t)c * NN + r0, acc[m][n][0]);
                atomicAdd(g_P + (size_t)(c + 1) * NN + r0, acc[m][n][1]);
                atomicAdd(g_P + (size_t)c * NN + r0 + 8, acc[m][n][2]);
                atomicAdd(g_P + (size_t)(c + 1) * NN + r0 + 8, acc[m][n][3]);
            }
        }
    }
}

// ---------------- fused combine + softmax v3: grid 256 x 256 thr ----------------
// block = 16 voxels x 16 label-chunks (2 labels each; chunk 10 has 1; 11..15 idle for matvec).
__global__ void __launch_bounds__(256) cs_k(const float* __restrict__ logits,
                                            float* __restrict__ out, int last) {
    __shared__ float Ms[LL * LL];
    __shared__ float Mb[LL * LL];
    __shared__ float redM[16][16];
    __shared__ float redS[16][16];
    int tid = threadIdx.x;
    for (int i = tid; i < LL * LL; i += 256) {
        Ms[i] = g_Msp[i];
        Mb[i] = g_Mbi[i];
    }
    __syncthreads();

    int w = tid & 15;                 // voxel within block
    int chunk = tid >> 4;             // 0..15
    int n = blockIdx.x * 16 + w;
    int l0 = chunk * 2;               // labels l0, l0+1 (chunk 10: only l=20)
    int lcnt = (l0 + 2 <= LL) ? 2 : (l0 < LL ? 1 : 0);

    int z = n >> 8, y = (n >> 4) & 15, x = n & 15;
    float invs = 1.f / (g_S[z] * g_S[y] * g_S[x]);

    float p[22];
#pragma unroll
    for (int m = 0; m < 22; m++) p[m] = g_P[m * NN + n];
    float invb = 1.f / p[21];
    float a[LL];
#pragma unroll
    for (int m = 0; m < LL; m++) a[m] = g_A[m * NN + n];

    float val[2];
    float mx = -1e30f;
#pragma unroll
    for (int j = 0; j < 2; j++) {
        if (j < lcnt) {
            int l = l0 + j;
            const float* ms = Ms + l * LL;
            const float* mb = Mb + l * LL;
            float ssp = 0.f, sbi = 0.f;
#pragma unroll
            for (int m = 0; m < LL; m++) {
                ssp += ms[m] * a[m];
                sbi += mb[m] * p[m];
            }
            float v = logits[l * NN + n] + ssp * invs + sbi * invb;
            val[j] = v;
            mx = fmaxf(mx, v);
        }
    }

    if (last) {
#pragma unroll
        for (int j = 0; j < 2; j++)
            if (j < lcnt) out[(l0 + j) * NN + n] = val[j];
        return;
    }

    redM[chunk][w] = mx;
    __syncthreads();
    float gmx = redM[0][w];
#pragma unroll
    for (int c = 1; c < 11; c++) gmx = fmaxf(gmx, redM[c][w]);

    float psum = 0.f;
#pragma unroll
    for (int j = 0; j < 2; j++) {
        if (j < lcnt) {
            val[j] = __expf(val[j] - gmx);
            psum += val[j];
        }
    }
    redS[chunk][w] = psum;
    __syncthreads();
    float s = redS[0][w];
#pragma unroll
    for (int c = 1; c < 11; c++) s += redS[c][w];
    float inv = 1.f / s;

#pragma unroll
    for (int j = 0; j < 2; j++) {
        if (j < lcnt) {
            float q = val[j] * inv;
            g_q[(l0 + j) * NN + n] = q;
            g_qb[(l0 + j) * NN + n] = __float2bfloat16(q);
        }
    }
    // zero P rows for next iteration: chunk c zeroes rows 2c, 2c+1 (coalesced)
    g_P[(chunk * 2) * NN + n] = 0.f;
    g_P[(chunk * 2 + 1) * NN + n] = 0.f;
}

// ---------------- host launch ----------------
extern "C" void kernel_launch(void* const* d_in, const int* in_sizes, int n_in,
                              void* d_out, int out_size) {
    (void)in_sizes; (void)n_in; (void)out_size;
    const float* image  = (const float*)d_in[0];
    const float* logits = (const float*)d_in[1];
    const float* wsp    = (const float*)d_in[2];
    const float* wbi    = (const float*)d_in[3];
    const float* comp   = (const float*)d_in[4];
    float* out = (float*)d_out;

    featsm_k<<<33, 128>>>(image, logits, wsp, wbi, comp);
    buildK_k<<<dim3(16, 128), 128>>>();

    for (int it = 0; it < 5; it++) {
        sg_k<<<533, 256>>>();
        cs_k<<<256, 256>>>(logits, out, it == 4 ? 1 : 0);
    }
}